// round 16
// baseline (speedup 1.0000x reference)
#include <cuda_runtime.h>
#include <cuda_fp16.h>
#include <cstdint>

// Shapes (fixed): inputs (B=32,C=256,H=64,W=64) f32; biases (1,1,C=256,F=256) f32
// out (B=32,F=256,H=64,W=64) f32.
// Math: out = log( sum_c exp(x) * p[c,f] ), p = b^2 / sum_c b^2 (no max shift; safe).
#define CC 256
#define FF 256
#define HWX 4096
#define BB 32
#define TILE_M 64
#define THREADS 512
#define NCHUNK 4               // 4 chunks x 64 channels
#define A_BYTES (TILE_M * 512)            // 32 KB (64 rows x 256 fp16, XOR swizzle)
#define BCH_BYTES (FF * 128)              // 32 KB per chunk (256 f-rows x 128B)
#define SMEM_BYTES (A_BYTES + 2 * BCH_BYTES)   // 98304 B -> 2 CTAs/SM (32 warps)

// Weights fp16, transposed AND pre-swizzled row image: row f = 512B, 16B unit u
// stored at unit position (u ^ swk(f)). Swizzle stays within each 128B block.
__device__ __half g_w[FF * CC];

__device__ __forceinline__ uint32_t swk(uint32_t r) { return (r & 7u) ^ ((r >> 3) & 7u); }

__device__ __forceinline__ uint32_t h2_as_u32(__half2 h) {
    union { __half2 h; uint32_t u; } cvt; cvt.h = h; return cvt.u;
}

// One warp per filter f, 256 blocks: spreads the strided bias reads chip-wide.
__global__ void compute_w_kernel(const float* __restrict__ biases) {
    const int lane = threadIdx.x & 31;
    const int f = blockIdx.x;
    float v[8];
    float s = 0.f;
    #pragma unroll
    for (int k = 0; k < 8; ++k) {
        v[k] = biases[(k * 32 + lane) * FF + f];
        s = fmaf(v[k], v[k], s);
    }
    #pragma unroll
    for (int o = 16; o > 0; o >>= 1) s += __shfl_xor_sync(0xffffffffu, s, o);
    const float inv = 1.0f / s;
    const uint32_t sw = swk((uint32_t)f);
    #pragma unroll
    for (int k = 0; k < 8; ++k) {
        int c = k * 32 + lane;
        uint32_t u = (uint32_t)(c >> 3);
        uint32_t idx = (uint32_t)f * 256u + ((u ^ sw) << 3) + (uint32_t)(c & 7);
        g_w[idx] = __float2half_rn(v[k] * v[k] * inv);
    }
}

__device__ __forceinline__ void cp16(uint32_t dst, const void* src) {
    asm volatile("cp.async.cg.shared.global [%0], [%1], 16;" :: "r"(dst), "l"(src) : "memory");
}
__device__ __forceinline__ void ldsm4(uint32_t* r, uint32_t addr) {
    asm volatile("ldmatrix.sync.aligned.m8n8.x4.shared.b16 {%0,%1,%2,%3}, [%4];"
                 : "=r"(r[0]), "=r"(r[1]), "=r"(r[2]), "=r"(r[3]) : "r"(addr));
}
__device__ __forceinline__ void mma_f16(float* d, const uint32_t* a, uint32_t b0, uint32_t b1) {
    asm volatile(
        "mma.sync.aligned.m16n8k16.row.col.f32.f16.f16.f32 "
        "{%0,%1,%2,%3}, {%4,%5,%6,%7}, {%8,%9}, {%0,%1,%2,%3};"
        : "+f"(d[0]), "+f"(d[1]), "+f"(d[2]), "+f"(d[3])
        : "r"(a[0]), "r"(a[1]), "r"(a[2]), "r"(a[3]), "r"(b0), "r"(b1));
}

__global__ __launch_bounds__(THREADS, 2)
void mixture_mma_kernel(const float* __restrict__ x, float* __restrict__ out) {
    extern __shared__ __align__(16) char smem[];
    const uint32_t abase = (uint32_t)__cvta_generic_to_shared(smem);
    const uint32_t bbase = abase + A_BYTES;

    const int tid = threadIdx.x;
    const int b   = blockIdx.x >> 6;
    const int hw0 = (blockIdx.x & 63) * TILE_M;

    // ---- Pre-issue B chunk 0 (32 KB, dense memcpy of pre-swizzled image) ----
    {
        #pragma unroll
        for (int i = 0; i < 4; ++i) {
            int q = i * THREADS + tid;           // 2048 16B units
            int f = q >> 3, seg = q & 7;
            cp16(bbase + (uint32_t)(f * 128 + seg * 16),
                 (const char*)g_w + f * 512 + seg * 16);
        }
        asm volatile("cp.async.commit_group;" ::: "memory");
    }

    // ---- Phase 1: x -> regs (full MLP), then exp -> swizzled fp16 STS ----
    const int r   = tid & 63;                    // pixel within tile
    const int grp = tid >> 6;                    // 8 groups x 32 channels
    {
        const float* xb = x + ((long)b * CC + grp * 32) * HWX + hw0 + r;
        float4 xr[8];
        #pragma unroll
        for (int i = 0; i < 8; ++i) {
            xr[i].x = xb[(long)(4 * i + 0) * HWX];
            xr[i].y = xb[(long)(4 * i + 1) * HWX];
            xr[i].z = xb[(long)(4 * i + 2) * HWX];
            xr[i].w = xb[(long)(4 * i + 3) * HWX];
        }
        const uint32_t sw = swk((uint32_t)r);
        const uint32_t ab = abase + (uint32_t)r * 512;
        #pragma unroll
        for (int i = 0; i < 8; ++i) {
            __half2 h01 = __floats2half2_rn(__expf(xr[i].x), __expf(xr[i].y));
            __half2 h23 = __floats2half2_rn(__expf(xr[i].z), __expf(xr[i].w));
            uint32_t c16 = (uint32_t)(grp * 4 + (i >> 1));
            uint32_t addr = ab + ((c16 ^ sw) << 4) + ((i & 1) << 3);
            asm volatile("st.shared.v2.u32 [%0], {%1, %2};"
                         :: "r"(addr), "r"(h2_as_u32(h01)), "r"(h2_as_u32(h23)));
        }
    }

    // ---- MMA setup: warp grid 2(M) x 8(N), warp tile 32M x 32N ----
    const int lane = tid & 31, wid = tid >> 5;
    const int g = lane >> 2, tig = lane & 3;
    const int wm = wid >> 3, wn = wid & 7;
    const int row0 = wm * 32;
    const int n0 = wn * 32;

    const int lm = lane >> 3, lr = lane & 7;
    const uint32_t ksel = (uint32_t)(lm >> 1);
    const uint32_t a_row0 = (uint32_t)(row0 + ((lm & 1) << 3) + lr);
    const uint32_t a_row1 = a_row0 + 16;
    const uint32_t a0base = abase + a_row0 * 512;
    const uint32_t a1base = abase + a_row1 * 512;
    const uint32_t sw_a0 = swk(a_row0), sw_a1 = swk(a_row1);
    const uint32_t b_row = (uint32_t)(((lm & 1) << 3) + lr);
    uint32_t foff[2], sw_b[2];
    #pragma unroll
    for (int j = 0; j < 2; ++j) {
        uint32_t frow = (uint32_t)(n0 + j * 16) + b_row;
        foff[j] = frow * 128;
        sw_b[j] = swk(frow);
    }

    float acc[2][4][4];
    #pragma unroll
    for (int t = 0; t < 2; ++t)
        #pragma unroll
        for (int j = 0; j < 4; ++j)
            #pragma unroll
            for (int q = 0; q < 4; ++q) acc[t][j][q] = 0.f;

    // ---- Mainloop: 4 chunks x 4 ksteps; ONE barrier per chunk ----
    for (int c = 0; c < NCHUNK; ++c) {
        asm volatile("cp.async.wait_group 0;" ::: "memory");   // chunk c landed
        __syncthreads();             // c visible to all; prev compute done
        if (c + 1 < NCHUNK) {        // issue c+1 into other stage (overlaps compute)
            const uint32_t sb = bbase + (uint32_t)(((c + 1) & 1) * BCH_BYTES);
            const char* src = (const char*)g_w + (c + 1) * 128;
            #pragma unroll
            for (int i = 0; i < 4; ++i) {
                int q = i * THREADS + tid;
                int f = q >> 3, seg = q & 7;
                cp16(sb + (uint32_t)(f * 128 + seg * 16), src + f * 512 + seg * 16);
            }
            asm volatile("cp.async.commit_group;" ::: "memory");
        }

        const uint32_t bbuf = bbase + (uint32_t)((c & 1) * BCH_BYTES);
        const uint32_t ahi = (uint32_t)(c * 128);              // A chunk offset
        #pragma unroll
        for (int ks = 0; ks < 4; ++ks) {
            const uint32_t klo = (uint32_t)(2 * ks) + ksel;    // low-3-bit unit idx
            uint32_t a0[4], a1[4];
            ldsm4(a0, a0base + ahi + ((klo ^ sw_a0) << 4));
            ldsm4(a1, a1base + ahi + ((klo ^ sw_a1) << 4));
            #pragma unroll
            for (int j = 0; j < 2; ++j) {
                uint32_t bf[4];
                ldsm4(bf, bbuf + foff[j] + ((klo ^ sw_b[j]) << 4));
                mma_f16(acc[0][2 * j],     a0, bf[0], bf[2]);
                mma_f16(acc[0][2 * j + 1], a0, bf[1], bf[3]);
                mma_f16(acc[1][2 * j],     a1, bf[0], bf[2]);
                mma_f16(acc[1][2 * j + 1], a1, bf[1], bf[3]);
            }
        }
    }

    // ---- Epilogue: direct scattered STG (full 32B sectors, no staging) ----
    {
        float* ob = out + (long)b * FF * HWX + hw0;
        #pragma unroll
        for (int t = 0; t < 2; ++t) {
            const int rb = row0 + t * 16 + g;
            #pragma unroll
            for (int j = 0; j < 4; ++j) {
                const int f = n0 + j * 8 + 2 * tig;
                float* p0 = ob + (long)f * HWX + rb;
                p0[0]       = __logf(acc[t][j][0]);
                p0[HWX]     = __logf(acc[t][j][1]);
                p0[8]       = __logf(acc[t][j][2]);
                p0[HWX + 8] = __logf(acc[t][j][3]);
            }
        }
    }
}

extern "C" void kernel_launch(void* const* d_in, const int* in_sizes, int n_in,
                              void* d_out, int out_size) {
    const float* inputs = (const float*)d_in[0];
    const float* biases = (const float*)d_in[1];
    if (n_in >= 2 && in_sizes[0] == CC * FF) {   // defensive order swap
        biases = (const float*)d_in[0];
        inputs = (const float*)d_in[1];
    }
    float* out = (float*)d_out;

    cudaFuncSetAttribute(mixture_mma_kernel,
                         cudaFuncAttributeMaxDynamicSharedMemorySize, SMEM_BYTES);
    compute_w_kernel<<<FF, 32>>>(biases);
    mixture_mma_kernel<<<BB * (HWX / TILE_M), THREADS, SMEM_BYTES>>>(inputs, out);
}

// round 17
// speedup vs baseline: 1.2345x; 1.2345x over previous
#include <cuda_runtime.h>
#include <cuda_fp16.h>
#include <cstdint>

// Shapes (fixed): inputs (B=32,C=256,H=64,W=64) f32; biases (1,1,C=256,F=256) f32
// out (B=32,F=256,H=64,W=64) f32.
// Math: out = log( sum_c exp(x) * p[c,f] ), p = b^2 / sum_c b^2 (no max shift; safe).
#define CC 256
#define FF 256
#define HWX 4096
#define BB 32
#define TILE_M 64
#define NCHUNK 4               // 4 chunks x 64 channels
#define A_BYTES (TILE_M * 512)            // 32 KB (64 rows x 256 fp16, XOR swizzle)
#define BCH_BYTES (FF * 128)              // 32 KB per chunk (256 f-rows x 128B)
#define SMEM_BYTES (A_BYTES + 2 * BCH_BYTES)   // 98304 B -> 2 CTAs/SM

// Weights fp16, transposed AND pre-swizzled row image: row f = 512B, 16B unit u
// stored at unit position (u ^ swk(f)). Swizzle stays within each 128B block.
__device__ __half g_w[FF * CC];

__device__ __forceinline__ uint32_t swk(uint32_t r) { return (r & 7u) ^ ((r >> 3) & 7u); }

__device__ __forceinline__ uint32_t h2_as_u32(__half2 h) {
    union { __half2 h; uint32_t u; } cvt; cvt.h = h; return cvt.u;
}

// One warp per filter f, 256 blocks: spreads the strided bias reads chip-wide.
__global__ void compute_w_kernel(const float* __restrict__ biases) {
    const int lane = threadIdx.x & 31;
    const int f = blockIdx.x;
    float v[8];
    float s = 0.f;
    #pragma unroll
    for (int k = 0; k < 8; ++k) {
        v[k] = biases[(k * 32 + lane) * FF + f];
        s = fmaf(v[k], v[k], s);
    }
    #pragma unroll
    for (int o = 16; o > 0; o >>= 1) s += __shfl_xor_sync(0xffffffffu, s, o);
    const float inv = 1.0f / s;
    const uint32_t sw = swk((uint32_t)f);
    #pragma unroll
    for (int k = 0; k < 8; ++k) {
        int c = k * 32 + lane;
        uint32_t u = (uint32_t)(c >> 3);
        uint32_t idx = (uint32_t)f * 256u + ((u ^ sw) << 3) + (uint32_t)(c & 7);
        g_w[idx] = __float2half_rn(v[k] * v[k] * inv);
    }
}

__device__ __forceinline__ void cp16(uint32_t dst, const void* src) {
    asm volatile("cp.async.cg.shared.global [%0], [%1], 16;" :: "r"(dst), "l"(src) : "memory");
}
__device__ __forceinline__ void ldsm4(uint32_t* r, uint32_t addr) {
    asm volatile("ldmatrix.sync.aligned.m8n8.x4.shared.b16 {%0,%1,%2,%3}, [%4];"
                 : "=r"(r[0]), "=r"(r[1]), "=r"(r[2]), "=r"(r[3]) : "r"(addr));
}
__device__ __forceinline__ void mma_f16(float* d, const uint32_t* a, uint32_t b0, uint32_t b1) {
    asm volatile(
        "mma.sync.aligned.m16n8k16.row.col.f32.f16.f16.f32 "
        "{%0,%1,%2,%3}, {%4,%5,%6,%7}, {%8,%9}, {%0,%1,%2,%3};"
        : "+f"(d[0]), "+f"(d[1]), "+f"(d[2]), "+f"(d[3])
        : "r"(a[0]), "r"(a[1]), "r"(a[2]), "r"(a[3]), "r"(b0), "r"(b1));
}

__global__ __launch_bounds__(256, 2)
void mixture_mma_kernel(const float* __restrict__ x, float* __restrict__ out) {
    extern __shared__ __align__(16) char smem[];
    const uint32_t abase = (uint32_t)__cvta_generic_to_shared(smem);
    const uint32_t bbase = abase + A_BYTES;

    const int tid = threadIdx.x;
    const int b   = blockIdx.x >> 6;
    const int hw0 = (blockIdx.x & 63) * TILE_M;

    // ---- Pre-issue B chunk 0 (32 KB, dense memcpy of pre-swizzled image) ----
    {
        #pragma unroll
        for (int i = 0; i < 8; ++i) {
            int q = i * 256 + tid;               // 2048 16B units
            int f = q >> 3, seg = q & 7;
            cp16(bbase + (uint32_t)(f * 128 + seg * 16),
                 (const char*)g_w + f * 512 + seg * 16);
        }
        asm volatile("cp.async.commit_group;" ::: "memory");
    }

    // ---- Phase 1: x -> regs (full MLP), then exp -> swizzled v4 STS (16B) ----
    const int r   = tid & 63;                    // pixel within tile
    const int grp = tid >> 6;                    // 4 groups x 64 channels
    {
        const float* xb = x + ((long)b * CC + grp * 64) * HWX + hw0 + r;
        float4 xr[16];
        #pragma unroll
        for (int i = 0; i < 16; ++i) {
            xr[i].x = xb[(long)(4 * i + 0) * HWX];
            xr[i].y = xb[(long)(4 * i + 1) * HWX];
            xr[i].z = xb[(long)(4 * i + 2) * HWX];
            xr[i].w = xb[(long)(4 * i + 3) * HWX];
        }
        const uint32_t sw = swk((uint32_t)r);
        const uint32_t ab = abase + (uint32_t)r * 512;
        #pragma unroll
        for (int u = 0; u < 8; ++u) {            // one 16B unit = 8 channels
            __half2 h0 = __floats2half2_rn(__expf(xr[2*u].x),   __expf(xr[2*u].y));
            __half2 h1 = __floats2half2_rn(__expf(xr[2*u].z),   __expf(xr[2*u].w));
            __half2 h2 = __floats2half2_rn(__expf(xr[2*u+1].x), __expf(xr[2*u+1].y));
            __half2 h3 = __floats2half2_rn(__expf(xr[2*u+1].z), __expf(xr[2*u+1].w));
            uint32_t c16 = (uint32_t)(grp * 8 + u);
            uint32_t addr = ab + ((c16 ^ sw) << 4);
            asm volatile("st.shared.v4.b32 [%0], {%1, %2, %3, %4};"
                         :: "r"(addr), "r"(h2_as_u32(h0)), "r"(h2_as_u32(h1)),
                            "r"(h2_as_u32(h2)), "r"(h2_as_u32(h3)));
        }
    }

    // ---- MMA setup: warp grid 2(M) x 4(N), warp tile 32M x 64N ----
    const int lane = tid & 31, wid = tid >> 5;
    const int g = lane >> 2, tig = lane & 3;
    const int wm = wid >> 2, wn = wid & 3;
    const int row0 = wm * 32;
    const int n0 = wn * 64;

    const int lm = lane >> 3, lr = lane & 7;
    const uint32_t ksel = (uint32_t)(lm >> 1);
    const uint32_t a_row0 = (uint32_t)(row0 + ((lm & 1) << 3) + lr);
    const uint32_t a_row1 = a_row0 + 16;
    const uint32_t a0base = abase + a_row0 * 512;
    const uint32_t a1base = abase + a_row1 * 512;
    const uint32_t sw_a0 = swk(a_row0), sw_a1 = swk(a_row1);
    const uint32_t b_row = (uint32_t)(((lm & 1) << 3) + lr);
    uint32_t foff[4], sw_b[4];
    #pragma unroll
    for (int j = 0; j < 4; ++j) {
        uint32_t frow = (uint32_t)(n0 + j * 16) + b_row;
        foff[j] = frow * 128;
        sw_b[j] = swk(frow);
    }

    float acc[2][8][4];
    #pragma unroll
    for (int t = 0; t < 2; ++t)
        #pragma unroll
        for (int j = 0; j < 8; ++j)
            #pragma unroll
            for (int q = 0; q < 4; ++q) acc[t][j][q] = 0.f;

    // ---- Mainloop: 4 chunks x 4 ksteps; fully unrolled; 1 barrier/chunk ----
    #pragma unroll
    for (int c = 0; c < NCHUNK; ++c) {
        asm volatile("cp.async.wait_group 0;" ::: "memory");   // chunk c landed
        __syncthreads();             // c visible to all; prev compute done
        if (c + 1 < NCHUNK) {        // issue c+1 into other stage (overlaps compute)
            const uint32_t sb = bbase + (uint32_t)(((c + 1) & 1) * BCH_BYTES);
            const char* src = (const char*)g_w + (c + 1) * 128;
            #pragma unroll
            for (int i = 0; i < 8; ++i) {
                int q = i * 256 + tid;
                int f = q >> 3, seg = q & 7;
                cp16(sb + (uint32_t)(f * 128 + seg * 16), src + f * 512 + seg * 16);
            }
            asm volatile("cp.async.commit_group;" ::: "memory");
        }

        const uint32_t bbuf = bbase + (uint32_t)((c & 1) * BCH_BYTES);
        const uint32_t ahi = (uint32_t)(c * 128);              // A chunk offset
        #pragma unroll
        for (int ks = 0; ks < 4; ++ks) {
            const uint32_t klo = (uint32_t)(2 * ks) + ksel;    // low-3-bit unit idx
            uint32_t a0[4], a1[4];
            ldsm4(a0, a0base + ahi + ((klo ^ sw_a0) << 4));
            ldsm4(a1, a1base + ahi + ((klo ^ sw_a1) << 4));
            #pragma unroll
            for (int j = 0; j < 4; ++j) {
                uint32_t bf[4];
                ldsm4(bf, bbuf + foff[j] + ((klo ^ sw_b[j]) << 4));
                mma_f16(acc[0][2 * j],     a0, bf[0], bf[2]);
                mma_f16(acc[0][2 * j + 1], a0, bf[1], bf[3]);
                mma_f16(acc[1][2 * j],     a1, bf[0], bf[2]);
                mma_f16(acc[1][2 * j + 1], a1, bf[1], bf[3]);
            }
        }
    }

    // ---- Epilogue: direct scattered STG, strength-reduced addressing ----
    {
        // base pointer for this thread: filter n0 + 2*tig, pixel row0 + g
        float* pbase = out + ((long)b * FF + (n0 + 2 * tig)) * HWX + hw0 + row0 + g;
        #pragma unroll
        for (int t = 0; t < 2; ++t) {
            float* pt = pbase + t * 16;          // pixel += 16
            #pragma unroll
            for (int j = 0; j < 8; ++j) {
                float* p0 = pt + (long)j * (8 * HWX);   // filter += 8
                p0[0]       = __logf(acc[t][j][0]);
                p0[HWX]     = __logf(acc[t][j][1]);
                p0[8]       = __logf(acc[t][j][2]);
                p0[HWX + 8] = __logf(acc[t][j][3]);
            }
        }
    }
}

extern "C" void kernel_launch(void* const* d_in, const int* in_sizes, int n_in,
                              void* d_out, int out_size) {
    const float* inputs = (const float*)d_in[0];
    const float* biases = (const float*)d_in[1];
    if (n_in >= 2 && in_sizes[0] == CC * FF) {   // defensive order swap
        biases = (const float*)d_in[0];
        inputs = (const float*)d_in[1];
    }
    float* out = (float*)d_out;

    cudaFuncSetAttribute(mixture_mma_kernel,
                         cudaFuncAttributeMaxDynamicSharedMemorySize, SMEM_BYTES);
    compute_w_kernel<<<FF, 32>>>(biases);
    mixture_mma_kernel<<<BB * (HWX / TILE_M), 256, SMEM_BYTES>>>(inputs, out);
}